// round 12
// baseline (speedup 1.0000x reference)
#include <cuda_runtime.h>
#include <float.h>
#include <stdint.h>

#define NJOINT 17
#define HH 512
#define WW 512
#define HW (HH * WW)
#define TOPK 30
#define MAXPEAKS 16384
#define HICAP 1024
#define HTHR 0.999f

// ---------------- scratch (device globals, zero-init at module load) --------
__device__ int    g_count[NJOINT];
__device__ int    g_cnth[NJOINT];
__device__ float  g_pval[NJOINT][MAXPEAKS];
__device__ int    g_pidx[NJOINT][MAXPEAKS];
__device__ float  g_hval[NJOINT][HICAP];
__device__ int    g_hidx[NJOINT][HICAP];
__device__ float2 g_hxy[NJOINT][TOPK];

// ---------------- packed f32x2 helpers --------------------------------------
__device__ __forceinline__ unsigned long long pk2(float lo, float hi) {
    unsigned long long r;
    asm("mov.b64 %0, {%1, %2};" : "=l"(r) : "f"(lo), "f"(hi));
    return r;
}
__device__ __forceinline__ void upk2(float& lo, float& hi, unsigned long long v) {
    asm("mov.b64 {%0, %1}, %2;" : "=f"(lo), "=f"(hi) : "l"(v));
}
__device__ __forceinline__ unsigned long long add2(unsigned long long a, unsigned long long b) {
    unsigned long long r;
    asm("add.rn.f32x2 %0, %1, %2;" : "=l"(r) : "l"(a), "l"(b));
    return r;
}
__device__ __forceinline__ unsigned long long mul2(unsigned long long a, unsigned long long b) {
    unsigned long long r;
    asm("mul.rn.f32x2 %0, %1, %2;" : "=l"(r) : "l"(a), "l"(b));
    return r;
}
__device__ __forceinline__ unsigned long long fma2(unsigned long long a, unsigned long long b,
                                                   unsigned long long c) {
    unsigned long long r;
    asm("fma.rn.f32x2 %0, %1, %2, %3;" : "=l"(r) : "l"(a), "l"(b), "l"(c));
    return r;
}

// ---------------- kernel 1: 5x5 NMS + peak compaction -----------------------
// Tile 128x16 output, 512 threads (4 blocks/SM co-resident to hide barriers).
#define TW 128
#define TH 16
#define LR (TH + 4)      // 20 loaded rows
#define LCV 35           // float4s per row (140 cols)
#define SPITCH 144       // padded row pitch in floats
#define STAGE 256
#define NMS_T 512

__global__ void __launch_bounds__(NMS_T) nms_kernel(const float* __restrict__ heat) {
    __shared__ float s[LR][SPITCH];   // 11.5 KB
    __shared__ float rm[LR][TW];      // 10.2 KB
    __shared__ float stv[STAGE];
    __shared__ int   sti[STAGE];
    __shared__ int   scnt;
    __shared__ int   sbase;

    const int tid  = threadIdx.x;
    const int j    = blockIdx.z;
    const int gx0a = blockIdx.x * TW - 4;   // 4-aligned tile base
    const int gy0  = blockIdx.y * TH - 2;
    const float* hj = heat + (size_t)j * HW;

    if (tid == 0) scnt = 0;

    // ---- load: mostly float4, per-task fallback at borders ----
    for (int i = tid; i < LR * LCV; i += NMS_T) {
        int ly = i / LCV, lx4 = i - ly * LCV;
        int gy = gy0 + ly;
        int gxs = gx0a + 4 * lx4;
        float4 v;
        bool rowIn = ((unsigned)gy < HH);
        if (rowIn && gxs >= 0 && gxs + 3 < WW) {
            v = __ldg((const float4*)(hj + gy * WW + gxs));
        } else if (rowIn) {
            v.x = ((unsigned)(gxs + 0) < WW) ? __ldg(hj + gy * WW + gxs + 0) : -FLT_MAX;
            v.y = ((unsigned)(gxs + 1) < WW) ? __ldg(hj + gy * WW + gxs + 1) : -FLT_MAX;
            v.z = ((unsigned)(gxs + 2) < WW) ? __ldg(hj + gy * WW + gxs + 2) : -FLT_MAX;
            v.w = ((unsigned)(gxs + 3) < WW) ? __ldg(hj + gy * WW + gxs + 3) : -FLT_MAX;
        } else {
            v = make_float4(-FLT_MAX, -FLT_MAX, -FLT_MAX, -FLT_MAX);
        }
        *(float4*)&s[ly][4 * lx4] = v;
    }
    __syncthreads();

    // ---- horizontal 5-max: 4 outputs/task via float4 ----
    for (int i = tid; i < LR * 32; i += NMS_T) {
        int ly = i >> 5, q = i & 31;
        float4 a = *(const float4*)&s[ly][4 * q];       // v0..v3
        float4 b = *(const float4*)&s[ly][4 * q + 4];   // v4..v7
        float4 c = *(const float4*)&s[ly][4 * q + 8];   // v8..v11
        float v2 = a.z, v3 = a.w;
        float v4 = b.x, v5 = b.y, v6 = b.z, v7 = b.w;
        float v8 = c.x, v9 = c.y;
        float m34 = fmaxf(v3, v4), m56 = fmaxf(v5, v6), m78 = fmaxf(v7, v8);
        float4 o;
        o.x = fmaxf(v2, fmaxf(m34, m56));
        o.y = fmaxf(m34, fmaxf(m56, v7));
        o.z = fmaxf(v4, fmaxf(m56, m78));
        o.w = fmaxf(m56, fmaxf(m78, v9));
        *(float4*)&rm[ly][4 * q] = o;
    }
    __syncthreads();

    // ---- vertical 5-max, 4 output rows per thread (shared partials) ----
    {
        const int tx  = tid & 127;
        const int ty0 = (tid >> 7) * 4;      // 0,4,8,12
        float a0 = rm[ty0 + 0][tx], a1 = rm[ty0 + 1][tx];
        float a2 = rm[ty0 + 2][tx], a3 = rm[ty0 + 3][tx];
        float a4 = rm[ty0 + 4][tx], a5 = rm[ty0 + 5][tx];
        float a6 = rm[ty0 + 6][tx], a7 = rm[ty0 + 7][tx];
        float t12 = fmaxf(a1, a2), t34 = fmaxf(a3, a4), t56 = fmaxf(a5, a6);
        float mm[4];
        mm[0] = fmaxf(a0, fmaxf(t12, t34));
        mm[1] = fmaxf(t12, fmaxf(t34, a5));
        mm[2] = fmaxf(a2, fmaxf(t34, t56));
        mm[3] = fmaxf(t34, fmaxf(t56, a7));
        float cc[4];
        cc[0] = s[ty0 + 2][tx + 4];
        cc[1] = s[ty0 + 3][tx + 4];
        cc[2] = s[ty0 + 4][tx + 4];
        cc[3] = s[ty0 + 5][tx + 4];
        const int gx  = blockIdx.x * TW + tx;
        const int gyb = blockIdx.y * TH + ty0;
#pragma unroll
        for (int r = 0; r < 4; r++) {
            if (cc[r] == mm[r]) {
                int idx = (gyb + r) * WW + gx;
                int p = atomicAdd(&scnt, 1);
                if (p < STAGE) { stv[p] = cc[r]; sti[p] = idx; }
                if (cc[r] > HTHR) {
                    int hp = atomicAdd(&g_cnth[j], 1);
                    if (hp < HICAP) { g_hval[j][hp] = cc[r]; g_hidx[j][hp] = idx; }
                }
            }
        }
    }
    __syncthreads();

    if (tid == 0) sbase = atomicAdd(&g_count[j], min(scnt, STAGE));
    __syncthreads();

    const int cnt = min(scnt, STAGE), base = sbase;
    for (int i = tid; i < cnt; i += NMS_T) {
        int d = base + i;
        if (d < MAXPEAKS) {
            g_pval[j][d] = stv[i];
            g_pidx[j][d] = sti[i];
        }
    }
}

// ---------------- kernel 2: top-30 per joint + heat_xy ----------------------
__device__ __forceinline__ bool better(float v1, int i1, float v2, int i2) {
    // descending value, ascending index tie-break (jax.lax.top_k stable order)
    return (v1 > v2) || (v1 == v2 && i1 < i2);
}

template <int NR>
__device__ __forceinline__ void warp_top30(float* v, int* id, float* outv, int* outi) {
    for (int r = 0; r < TOPK; r++) {
        float bv = -FLT_MAX;
        int   bi = 0x7fffffff;
#pragma unroll
        for (int s = 0; s < NR; s++)
            if (better(v[s], id[s], bv, bi)) { bv = v[s]; bi = id[s]; }
#pragma unroll
        for (int o = 16; o > 0; o >>= 1) {
            float ov = __shfl_down_sync(0xffffffffu, bv, o);
            int   oi = __shfl_down_sync(0xffffffffu, bi, o);
            if (better(ov, oi, bv, bi)) { bv = ov; bi = oi; }
        }
        bv = __shfl_sync(0xffffffffu, bv, 0);
        bi = __shfl_sync(0xffffffffu, bi, 0);
        if ((threadIdx.x & 31) == 0) { outv[r] = bv; outi[r] = bi; }
#pragma unroll
        for (int s = 0; s < NR; s++)
            if (id[s] == bi) v[s] = -FLT_MAX;  // winner ids unique
    }
}

__global__ void __launch_bounds__(1024) topk_kernel(const float* __restrict__ off,
                                                    const int* __restrict__ stride_p) {
    __shared__ float wv1[32][TOPK];
    __shared__ int   wi1[32][TOPK];
    __shared__ float wv2[8][TOPK];
    __shared__ int   wi2[8][TOPK];
    __shared__ float fv[TOPK];
    __shared__ int   fi[TOPK];

    const int tid  = threadIdx.x;
    const int w    = tid >> 5;
    const int lane = tid & 31;
    const int j    = blockIdx.x;

    const int n_high = g_cnth[j];
    const bool useHigh = (n_high >= TOPK) && (n_high <= HICAP);

    if (useHigh) {
        float v[1];
        int   id[1];
        if (tid < n_high) { v[0] = g_hval[j][tid]; id[0] = g_hidx[j][tid]; }
        else              { v[0] = -FLT_MAX;       id[0] = 0x7fffffff;     }
        warp_top30<1>(v, id, wv1[w], wi1[w]);
    } else {
        int n = g_count[j];
        if (n > MAXPEAKS) n = MAXPEAKS;
        float v[16];
        int   id[16];
#pragma unroll
        for (int s = 0; s < 16; s++) {
            int i = tid + s * 1024;
            if (i < n) { v[s] = g_pval[j][i]; id[s] = g_pidx[j][i]; }
            else       { v[s] = -FLT_MAX;     id[s] = 0x7fffffff;   }
        }
        warp_top30<16>(v, id, wv1[w], wi1[w]);
    }
    __syncthreads();

    if (w < 8) {
        float v2[4];
        int   id2[4];
#pragma unroll
        for (int s = 0; s < 4; s++) {
            int e = lane + 32 * s;
            if (e < 4 * TOPK) {
                int L = w * 4 + e / TOPK, r = e % TOPK;
                v2[s] = wv1[L][r]; id2[s] = wi1[L][r];
            } else { v2[s] = -FLT_MAX; id2[s] = 0x7fffffff; }
        }
        warp_top30<4>(v2, id2, wv2[w], wi2[w]);
    }
    __syncthreads();

    if (w == 0) {
        float v3[8];
        int   id3[8];
#pragma unroll
        for (int s = 0; s < 8; s++) {
            int e = lane + 32 * s;
            if (e < 8 * TOPK) {
                int L = e / TOPK, r = e % TOPK;
                v3[s] = wv2[L][r]; id3[s] = wi2[L][r];
            } else { v3[s] = -FLT_MAX; id3[s] = 0x7fffffff; }
        }
        warp_top30<8>(v3, id3, fv, fi);
    }
    __syncthreads();

    if (tid < TOPK) {
        int idx = fi[tid];
        if (idx < 0 || idx >= HW) idx = 0;
        float x = (float)(idx & (WW - 1));
        float y = (float)(idx >> 9);
        float ox = __ldg(off + (size_t)(j * 2 + 0) * HW + idx);
        float oy = __ldg(off + (size_t)(j * 2 + 1) * HW + idx);
        float st = (float)(*stride_p);
        float2 r2;
        r2.x = __fmul_rn(st, __fadd_rn(x, ox));   // bit-exact vs reference
        r2.y = __fmul_rn(st, __fadd_rn(y, oy));
        g_hxy[j][tid] = r2;
    }

    // reset counters for next graph replay (all reads happened before syncs)
    if (tid == 0) { g_count[j] = 0; g_cnth[j] = 0; }
}

// ---------------- kernel 3: nearest-candidate assignment --------------------
// Warp-per-joint, lane-per-pose: block = 544 threads = 17 warps handles 32
// poses. Candidate LDS uniform per warp (broadcast); 1.7M threads for latency
// hiding. Pose I/O staged through shared (coalesced float2 both directions).
#define APB 32                      // poses per block
#define ABT (NJOINT * 32)           // 544 threads

__global__ void __launch_bounds__(ABT) assign_kernel(const float* __restrict__ poses,
                                                     float* __restrict__ out,
                                                     int N) {
    __shared__ unsigned long long sCX[NJOINT][16];  // packed (-x0,-x1) pairs
    __shared__ unsigned long long sCY[NJOINT][16];
    __shared__ float tile[APB * 34];                // pose in, result out

    const int tid   = threadIdx.x;
    const int w     = tid >> 5;      // joint
    const int lane  = tid & 31;      // pose within block
    const int base  = blockIdx.x * APB;
    const int npose = min(APB, N - base);

    for (int i = tid; i < NJOINT * (TOPK / 2); i += ABT) {
        int jj = i / (TOPK / 2), q = i % (TOPK / 2);
        float2 a = g_hxy[jj][2 * q];
        float2 b = g_hxy[jj][2 * q + 1];
        sCX[jj][q] = pk2(-a.x, -b.x);
        sCY[jj][q] = pk2(-a.y, -b.y);
    }
    {   // coalesced pose tile load (float2), one element per thread
        const float2* src = (const float2*)(poses + (size_t)base * 34);
        float2* dst = (float2*)tile;
        for (int i = tid; i < npose * NJOINT; i += ABT) dst[i] = src[i];
    }
    __syncthreads();

    if (lane < npose) {
        const int j = w;
        const float px = tile[lane * 34 + 2 * j];
        const float py = tile[lane * 34 + 2 * j + 1];
        const unsigned long long pxx = pk2(px, px);
        const unsigned long long pyy = pk2(py, py);

        float d2a[TOPK];
#pragma unroll
        for (int q = 0; q < TOPK / 2; q++) {
            unsigned long long dx = add2(pxx, sCX[j][q]);
            unsigned long long dy = add2(pyy, sCY[j][q]);
            unsigned long long d2 = fma2(dy, dy, mul2(dx, dx));
            upk2(d2a[2 * q], d2a[2 * q + 1], d2);
        }

        // 4-chain min for ILP
        float b0 = d2a[0], b1 = d2a[1], b2 = d2a[2], b3 = d2a[3];
#pragma unroll
        for (int k = 4; k < TOPK; k += 4) {
            b0 = fminf(b0, d2a[k]);
            b1 = fminf(b1, d2a[k + 1]);
            b2 = fminf(b2, d2a[k + 2]);
            b3 = fminf(b3, d2a[k + 3]);
        }
        b0 = fminf(b0, d2a[28]); b1 = fminf(b1, d2a[29]);
        const float bd = fminf(fminf(b0, b1), fminf(b2, b3));

        // close-set count + first-occurrence argmin (descending overwrite)
        const float thr = __fmul_rn(bd, 1.0000012f);
        int best = 0, nclose = 0;
#pragma unroll
        for (int k = TOPK - 1; k >= 0; k--) {
            if (d2a[k] <= thr) nclose++;
            if (d2a[k] == bd) best = k;
        }

        if (nclose != 1) {
            // rare slow path: replicate reference verbatim (rn d2, IEEE sqrt,
            // first-occurrence argmin over sqrt values)
            float bs = FLT_MAX;
            best = 0;
            for (int k = 0; k < TOPK; k++) {
                float lo, hi, ncx, ncy;
                upk2(lo, hi, sCX[j][k >> 1]); ncx = (k & 1) ? hi : lo;
                upk2(lo, hi, sCY[j][k >> 1]); ncy = (k & 1) ? hi : lo;
                float dx = __fadd_rn(px, ncx);
                float dy = __fadd_rn(py, ncy);
                float d  = __fadd_rn(__fmul_rn(dx, dx), __fmul_rn(dy, dy));
                float sq = sqrtf(d);
                if (sq < bs) { bs = sq; best = k; }
            }
        }

        float lo, hi, rx, ry;
        upk2(lo, hi, sCX[j][best >> 1]);
        rx = (best & 1) ? -hi : -lo;
        upk2(lo, hi, sCY[j][best >> 1]);
        ry = (best & 1) ? -hi : -lo;

        tile[lane * 34 + 2 * j]     = rx;   // own slot; pose already consumed
        tile[lane * 34 + 2 * j + 1] = ry;
    }
    __syncthreads();

    {   // coalesced result store (float2)
        float2* dst = (float2*)(out + (size_t)base * 34);
        const float2* src = (const float2*)tile;
        for (int i = tid; i < npose * NJOINT; i += ABT) dst[i] = src[i];
    }
}

// ---------------- launch ----------------------------------------------------
extern "C" void kernel_launch(void* const* d_in, const int* in_sizes, int n_in,
                              void* d_out, int out_size) {
    const float* poses    = (const float*)d_in[0];   // (N, 34) f32
    const float* heat     = (const float*)d_in[1];   // (17, 512, 512) f32
    const float* off      = (const float*)d_in[2];   // (17, 2, 512, 512) f32
    const int*   stride_p = (const int*)d_in[3];     // scalar

    const int N = in_sizes[0] / 34;

    dim3 g_nms(WW / TW, HH / TH, NJOINT);            // (4, 32, 17)
    nms_kernel<<<g_nms, NMS_T>>>(heat);

    topk_kernel<<<NJOINT, 1024>>>(off, stride_p);

    assign_kernel<<<(N + APB - 1) / APB, ABT>>>(poses, (float*)d_out, N);
}

// round 13
// speedup vs baseline: 1.0029x; 1.0029x over previous
#include <cuda_runtime.h>
#include <float.h>
#include <stdint.h>

#define NJOINT 17
#define HH 512
#define WW 512
#define HW (HH * WW)
#define TOPK 30
#define MAXPEAKS 16384
#define HICAP 1024
#define HTHR 0.999f

// ---------------- scratch (device globals, zero-init at module load) --------
__device__ int    g_count[NJOINT];
__device__ int    g_cnth[NJOINT];
__device__ float  g_pval[NJOINT][MAXPEAKS];
__device__ int    g_pidx[NJOINT][MAXPEAKS];
__device__ float  g_hval[NJOINT][HICAP];
__device__ int    g_hidx[NJOINT][HICAP];
__device__ float2 g_hxy[NJOINT][TOPK];

// ---------------- packed f32x2 helpers --------------------------------------
__device__ __forceinline__ unsigned long long pk2(float lo, float hi) {
    unsigned long long r;
    asm("mov.b64 %0, {%1, %2};" : "=l"(r) : "f"(lo), "f"(hi));
    return r;
}
__device__ __forceinline__ void upk2(float& lo, float& hi, unsigned long long v) {
    asm("mov.b64 {%0, %1}, %2;" : "=f"(lo), "=f"(hi) : "l"(v));
}
__device__ __forceinline__ unsigned long long add2(unsigned long long a, unsigned long long b) {
    unsigned long long r;
    asm("add.rn.f32x2 %0, %1, %2;" : "=l"(r) : "l"(a), "l"(b));
    return r;
}
__device__ __forceinline__ unsigned long long mul2(unsigned long long a, unsigned long long b) {
    unsigned long long r;
    asm("mul.rn.f32x2 %0, %1, %2;" : "=l"(r) : "l"(a), "l"(b));
    return r;
}
__device__ __forceinline__ unsigned long long fma2(unsigned long long a, unsigned long long b,
                                                   unsigned long long c) {
    unsigned long long r;
    asm("fma.rn.f32x2 %0, %1, %2, %3;" : "=l"(r) : "l"(a), "l"(b), "l"(c));
    return r;
}

// ---------------- kernel 1: 5x5 NMS + peak compaction -----------------------
// Tile 128x16 output, 512 threads (multi-block residency hides barriers).
#define TW 128
#define TH 16
#define LR (TH + 4)      // 20 loaded rows
#define LCV 35           // float4s per row (140 cols)
#define SPITCH 144       // padded row pitch in floats
#define STAGE 256
#define NMS_T 512

__global__ void __launch_bounds__(NMS_T) nms_kernel(const float* __restrict__ heat) {
    __shared__ float s[LR][SPITCH];
    __shared__ float rm[LR][TW];
    __shared__ float stv[STAGE];
    __shared__ int   sti[STAGE];
    __shared__ int   scnt;
    __shared__ int   sbase;

    const int tid  = threadIdx.x;
    const int j    = blockIdx.z;
    const int gx0a = blockIdx.x * TW - 4;   // 4-aligned tile base
    const int gy0  = blockIdx.y * TH - 2;
    const float* hj = heat + (size_t)j * HW;

    if (tid == 0) scnt = 0;

    // ---- load: mostly float4, per-task fallback at borders ----
    for (int i = tid; i < LR * LCV; i += NMS_T) {
        int ly = i / LCV, lx4 = i - ly * LCV;
        int gy = gy0 + ly;
        int gxs = gx0a + 4 * lx4;
        float4 v;
        bool rowIn = ((unsigned)gy < HH);
        if (rowIn && gxs >= 0 && gxs + 3 < WW) {
            v = __ldg((const float4*)(hj + gy * WW + gxs));
        } else if (rowIn) {
            v.x = ((unsigned)(gxs + 0) < WW) ? __ldg(hj + gy * WW + gxs + 0) : -FLT_MAX;
            v.y = ((unsigned)(gxs + 1) < WW) ? __ldg(hj + gy * WW + gxs + 1) : -FLT_MAX;
            v.z = ((unsigned)(gxs + 2) < WW) ? __ldg(hj + gy * WW + gxs + 2) : -FLT_MAX;
            v.w = ((unsigned)(gxs + 3) < WW) ? __ldg(hj + gy * WW + gxs + 3) : -FLT_MAX;
        } else {
            v = make_float4(-FLT_MAX, -FLT_MAX, -FLT_MAX, -FLT_MAX);
        }
        *(float4*)&s[ly][4 * lx4] = v;
    }
    __syncthreads();

    // ---- horizontal 5-max: 4 outputs/task via float4 ----
    for (int i = tid; i < LR * 32; i += NMS_T) {
        int ly = i >> 5, q = i & 31;
        float4 a = *(const float4*)&s[ly][4 * q];
        float4 b = *(const float4*)&s[ly][4 * q + 4];
        float4 c = *(const float4*)&s[ly][4 * q + 8];
        float v2 = a.z, v3 = a.w;
        float v4 = b.x, v5 = b.y, v6 = b.z, v7 = b.w;
        float v8 = c.x, v9 = c.y;
        float m34 = fmaxf(v3, v4), m56 = fmaxf(v5, v6), m78 = fmaxf(v7, v8);
        float4 o;
        o.x = fmaxf(v2, fmaxf(m34, m56));
        o.y = fmaxf(m34, fmaxf(m56, v7));
        o.z = fmaxf(v4, fmaxf(m56, m78));
        o.w = fmaxf(m56, fmaxf(m78, v9));
        *(float4*)&rm[ly][4 * q] = o;
    }
    __syncthreads();

    // ---- vertical 5-max, 4 output rows per thread (shared partials) ----
    {
        const int tx  = tid & 127;
        const int ty0 = (tid >> 7) * 4;
        float a0 = rm[ty0 + 0][tx], a1 = rm[ty0 + 1][tx];
        float a2 = rm[ty0 + 2][tx], a3 = rm[ty0 + 3][tx];
        float a4 = rm[ty0 + 4][tx], a5 = rm[ty0 + 5][tx];
        float a6 = rm[ty0 + 6][tx], a7 = rm[ty0 + 7][tx];
        float t12 = fmaxf(a1, a2), t34 = fmaxf(a3, a4), t56 = fmaxf(a5, a6);
        float mm[4];
        mm[0] = fmaxf(a0, fmaxf(t12, t34));
        mm[1] = fmaxf(t12, fmaxf(t34, a5));
        mm[2] = fmaxf(a2, fmaxf(t34, t56));
        mm[3] = fmaxf(t34, fmaxf(t56, a7));
        float cc[4];
        cc[0] = s[ty0 + 2][tx + 4];
        cc[1] = s[ty0 + 3][tx + 4];
        cc[2] = s[ty0 + 4][tx + 4];
        cc[3] = s[ty0 + 5][tx + 4];
        const int gx  = blockIdx.x * TW + tx;
        const int gyb = blockIdx.y * TH + ty0;
#pragma unroll
        for (int r = 0; r < 4; r++) {
            if (cc[r] == mm[r]) {
                int idx = (gyb + r) * WW + gx;
                int p = atomicAdd(&scnt, 1);
                if (p < STAGE) { stv[p] = cc[r]; sti[p] = idx; }
                if (cc[r] > HTHR) {
                    int hp = atomicAdd(&g_cnth[j], 1);
                    if (hp < HICAP) { g_hval[j][hp] = cc[r]; g_hidx[j][hp] = idx; }
                }
            }
        }
    }
    __syncthreads();

    if (tid == 0) sbase = atomicAdd(&g_count[j], min(scnt, STAGE));
    __syncthreads();

    const int cnt = min(scnt, STAGE), base = sbase;
    for (int i = tid; i < cnt; i += NMS_T) {
        int d = base + i;
        if (d < MAXPEAKS) {
            g_pval[j][d] = stv[i];
            g_pidx[j][d] = sti[i];
        }
    }
}

// ---------------- kernel 2: top-30 per joint + heat_xy ----------------------
__device__ __forceinline__ bool better(float v1, int i1, float v2, int i2) {
    // descending value, ascending index tie-break (jax.lax.top_k stable order)
    return (v1 > v2) || (v1 == v2 && i1 < i2);
}

template <int NR>
__device__ __forceinline__ void warp_top30(float* v, int* id, float* outv, int* outi) {
    for (int r = 0; r < TOPK; r++) {
        float bv = -FLT_MAX;
        int   bi = 0x7fffffff;
#pragma unroll
        for (int s = 0; s < NR; s++)
            if (better(v[s], id[s], bv, bi)) { bv = v[s]; bi = id[s]; }
#pragma unroll
        for (int o = 16; o > 0; o >>= 1) {
            float ov = __shfl_down_sync(0xffffffffu, bv, o);
            int   oi = __shfl_down_sync(0xffffffffu, bi, o);
            if (better(ov, oi, bv, bi)) { bv = ov; bi = oi; }
        }
        bv = __shfl_sync(0xffffffffu, bv, 0);
        bi = __shfl_sync(0xffffffffu, bi, 0);
        if ((threadIdx.x & 31) == 0) { outv[r] = bv; outi[r] = bi; }
#pragma unroll
        for (int s = 0; s < NR; s++)
            if (id[s] == bi) v[s] = -FLT_MAX;  // winner ids unique
    }
}

__global__ void __launch_bounds__(1024) topk_kernel(const float* __restrict__ off,
                                                    const int* __restrict__ stride_p) {
    __shared__ float wv1[32][TOPK];
    __shared__ int   wi1[32][TOPK];
    __shared__ float wv2[8][TOPK];
    __shared__ int   wi2[8][TOPK];
    __shared__ float fv[TOPK];
    __shared__ int   fi[TOPK];

    const int tid  = threadIdx.x;
    const int w    = tid >> 5;
    const int lane = tid & 31;
    const int j    = blockIdx.x;

    const int n_high = g_cnth[j];
    const bool useHigh = (n_high >= TOPK) && (n_high <= HICAP);

    if (useHigh) {
        float v[1];
        int   id[1];
        if (tid < n_high) { v[0] = g_hval[j][tid]; id[0] = g_hidx[j][tid]; }
        else              { v[0] = -FLT_MAX;       id[0] = 0x7fffffff;     }
        warp_top30<1>(v, id, wv1[w], wi1[w]);
    } else {
        int n = g_count[j];
        if (n > MAXPEAKS) n = MAXPEAKS;
        float v[16];
        int   id[16];
#pragma unroll
        for (int s = 0; s < 16; s++) {
            int i = tid + s * 1024;
            if (i < n) { v[s] = g_pval[j][i]; id[s] = g_pidx[j][i]; }
            else       { v[s] = -FLT_MAX;     id[s] = 0x7fffffff;   }
        }
        warp_top30<16>(v, id, wv1[w], wi1[w]);
    }
    __syncthreads();

    if (w < 8) {
        float v2[4];
        int   id2[4];
#pragma unroll
        for (int s = 0; s < 4; s++) {
            int e = lane + 32 * s;
            if (e < 4 * TOPK) {
                int L = w * 4 + e / TOPK, r = e % TOPK;
                v2[s] = wv1[L][r]; id2[s] = wi1[L][r];
            } else { v2[s] = -FLT_MAX; id2[s] = 0x7fffffff; }
        }
        warp_top30<4>(v2, id2, wv2[w], wi2[w]);
    }
    __syncthreads();

    if (w == 0) {
        float v3[8];
        int   id3[8];
#pragma unroll
        for (int s = 0; s < 8; s++) {
            int e = lane + 32 * s;
            if (e < 8 * TOPK) {
                int L = e / TOPK, r = e % TOPK;
                v3[s] = wv2[L][r]; id3[s] = wi2[L][r];
            } else { v3[s] = -FLT_MAX; id3[s] = 0x7fffffff; }
        }
        warp_top30<8>(v3, id3, fv, fi);
    }
    __syncthreads();

    if (tid < TOPK) {
        int idx = fi[tid];
        if (idx < 0 || idx >= HW) idx = 0;
        float x = (float)(idx & (WW - 1));
        float y = (float)(idx >> 9);
        float ox = __ldg(off + (size_t)(j * 2 + 0) * HW + idx);
        float oy = __ldg(off + (size_t)(j * 2 + 1) * HW + idx);
        float st = (float)(*stride_p);
        float2 r2;
        r2.x = __fmul_rn(st, __fadd_rn(x, ox));   // bit-exact vs reference
        r2.y = __fmul_rn(st, __fadd_rn(y, oy));
        g_hxy[j][tid] = r2;
    }

    // reset counters for next graph replay (all reads happened before syncs)
    if (tid == 0) { g_count[j] = 0; g_cnth[j] = 0; }
}

// ---------------- kernel 3: nearest-candidate assignment --------------------
// Warp-per-joint, lane-per-pose (544 thr = 17 warps x 32 poses). TWO-PASS
// min/argmin: pass 1 computes only the min (no d2 array -> ~30 regs -> 3
// blocks/SM resident); pass 2 recomputes identical packed d2 values descending
// k, overwriting best (first occurrence) and counting the close set.
#define APB 32
#define ABT (NJOINT * 32)           // 544 threads

__global__ void __launch_bounds__(ABT) assign_kernel(const float* __restrict__ poses,
                                                     float* __restrict__ out,
                                                     int N) {
    __shared__ unsigned long long sCX[NJOINT][16];  // packed (-x0,-x1) pairs
    __shared__ unsigned long long sCY[NJOINT][16];
    __shared__ float tile[APB * 34];                // pose in, result out

    const int tid   = threadIdx.x;
    const int w     = tid >> 5;      // joint
    const int lane  = tid & 31;      // pose within block
    const int base  = blockIdx.x * APB;
    const int npose = min(APB, N - base);

    for (int i = tid; i < NJOINT * (TOPK / 2); i += ABT) {
        int jj = i / (TOPK / 2), q = i % (TOPK / 2);
        float2 a = g_hxy[jj][2 * q];
        float2 b = g_hxy[jj][2 * q + 1];
        sCX[jj][q] = pk2(-a.x, -b.x);
        sCY[jj][q] = pk2(-a.y, -b.y);
    }
    {   // coalesced pose tile load (float2), one element per thread
        const float2* src = (const float2*)(poses + (size_t)base * 34);
        float2* dst = (float2*)tile;
        for (int i = tid; i < npose * NJOINT; i += ABT) dst[i] = src[i];
    }
    __syncthreads();

    if (lane < npose) {
        const int j = w;
        const float px = tile[lane * 34 + 2 * j];
        const float py = tile[lane * 34 + 2 * j + 1];
        const unsigned long long pxx = pk2(px, px);
        const unsigned long long pyy = pk2(py, py);

        // ---- pass 1: min only (2 chains, no storage) ----
        float bd0 = FLT_MAX, bd1 = FLT_MAX;
#pragma unroll
        for (int q = 0; q < TOPK / 2; q++) {
            unsigned long long dx = add2(pxx, sCX[j][q]);
            unsigned long long dy = add2(pyy, sCY[j][q]);
            unsigned long long d2 = fma2(dy, dy, mul2(dx, dx));
            float lo, hi;
            upk2(lo, hi, d2);
            bd0 = fminf(bd0, lo);
            bd1 = fminf(bd1, hi);
        }
        const float bd  = fminf(bd0, bd1);
        const float thr = __fmul_rn(bd, 1.0000012f);

        // ---- pass 2: recompute (bit-identical) descending; overwrite best
        //      (= first occurrence) and count close set ----
        int best = 0, nclose = 0;
#pragma unroll
        for (int q = TOPK / 2 - 1; q >= 0; q--) {
            unsigned long long dx = add2(pxx, sCX[j][q]);
            unsigned long long dy = add2(pyy, sCY[j][q]);
            unsigned long long d2 = fma2(dy, dy, mul2(dx, dx));
            float lo, hi;
            upk2(lo, hi, d2);
            if (hi <= thr) nclose++;
            if (hi == bd)  best = 2 * q + 1;
            if (lo <= thr) nclose++;
            if (lo == bd)  best = 2 * q;
        }

        if (nclose != 1) {
            // rare slow path: replicate reference verbatim (rn d2, IEEE sqrt,
            // first-occurrence argmin over sqrt values)
            float bs = FLT_MAX;
            best = 0;
            for (int k = 0; k < TOPK; k++) {
                float lo, hi, ncx, ncy;
                upk2(lo, hi, sCX[j][k >> 1]); ncx = (k & 1) ? hi : lo;
                upk2(lo, hi, sCY[j][k >> 1]); ncy = (k & 1) ? hi : lo;
                float dx = __fadd_rn(px, ncx);
                float dy = __fadd_rn(py, ncy);
                float d  = __fadd_rn(__fmul_rn(dx, dx), __fmul_rn(dy, dy));
                float sq = sqrtf(d);
                if (sq < bs) { bs = sq; best = k; }
            }
        }

        float lo, hi, rx, ry;
        upk2(lo, hi, sCX[j][best >> 1]);
        rx = (best & 1) ? -hi : -lo;
        upk2(lo, hi, sCY[j][best >> 1]);
        ry = (best & 1) ? -hi : -lo;

        tile[lane * 34 + 2 * j]     = rx;   // own slot; pose already consumed
        tile[lane * 34 + 2 * j + 1] = ry;
    }
    __syncthreads();

    {   // coalesced result store (float2)
        float2* dst = (float2*)(out + (size_t)base * 34);
        const float2* src = (const float2*)tile;
        for (int i = tid; i < npose * NJOINT; i += ABT) dst[i] = src[i];
    }
}

// ---------------- launch ----------------------------------------------------
extern "C" void kernel_launch(void* const* d_in, const int* in_sizes, int n_in,
                              void* d_out, int out_size) {
    const float* poses    = (const float*)d_in[0];   // (N, 34) f32
    const float* heat     = (const float*)d_in[1];   // (17, 512, 512) f32
    const float* off      = (const float*)d_in[2];   // (17, 2, 512, 512) f32
    const int*   stride_p = (const int*)d_in[3];     // scalar

    const int N = in_sizes[0] / 34;

    dim3 g_nms(WW / TW, HH / TH, NJOINT);            // (4, 32, 17)
    nms_kernel<<<g_nms, NMS_T>>>(heat);

    topk_kernel<<<NJOINT, 1024>>>(off, stride_p);

    assign_kernel<<<(N + APB - 1) / APB, ABT>>>(poses, (float*)d_out, N);
}

// round 17
// speedup vs baseline: 1.2746x; 1.2709x over previous
#include <cuda_runtime.h>
#include <float.h>
#include <stdint.h>

#define NJOINT 17
#define HH 512
#define WW 512
#define HW (HH * WW)
#define TOPK 30
#define MAXPEAKS 16384
#define HICAP 1024
#define HTHR 0.999f

// ---------------- scratch (device globals, zero-init at module load) --------
__device__ int    g_count[NJOINT];
__device__ int    g_cnth[NJOINT];
__device__ float  g_pval[NJOINT][MAXPEAKS];
__device__ int    g_pidx[NJOINT][MAXPEAKS];
__device__ float  g_hval[NJOINT][HICAP];
__device__ int    g_hidx[NJOINT][HICAP];
__device__ float2 g_hxy[NJOINT][TOPK];

// ---------------- packed f32x2 helpers --------------------------------------
__device__ __forceinline__ unsigned long long pk2(float lo, float hi) {
    unsigned long long r;
    asm("mov.b64 %0, {%1, %2};" : "=l"(r) : "f"(lo), "f"(hi));
    return r;
}
__device__ __forceinline__ void upk2(float& lo, float& hi, unsigned long long v) {
    asm("mov.b64 {%0, %1}, %2;" : "=f"(lo), "=f"(hi) : "l"(v));
}
__device__ __forceinline__ unsigned long long add2(unsigned long long a, unsigned long long b) {
    unsigned long long r;
    asm("add.rn.f32x2 %0, %1, %2;" : "=l"(r) : "l"(a), "l"(b));
    return r;
}
__device__ __forceinline__ unsigned long long mul2(unsigned long long a, unsigned long long b) {
    unsigned long long r;
    asm("mul.rn.f32x2 %0, %1, %2;" : "=l"(r) : "l"(a), "l"(b));
    return r;
}
__device__ __forceinline__ unsigned long long fma2(unsigned long long a, unsigned long long b,
                                                   unsigned long long c) {
    unsigned long long r;
    asm("fma.rn.f32x2 %0, %1, %2, %3;" : "=l"(r) : "l"(a), "l"(b), "l"(c));
    return r;
}

// ---------------- kernel 1: 5x5 NMS + peak compaction -----------------------
// Tile 128x16 output, 512 threads (multi-block residency hides barriers).
#define TW 128
#define TH 16
#define LR (TH + 4)      // 20 loaded rows
#define LCV 35           // float4s per row (140 cols)
#define SPITCH 144       // padded row pitch in floats
#define STAGE 256
#define NMS_T 512

__global__ void __launch_bounds__(NMS_T) nms_kernel(const float* __restrict__ heat) {
    __shared__ float s[LR][SPITCH];
    __shared__ float rm[LR][TW];
    __shared__ float stv[STAGE];
    __shared__ int   sti[STAGE];
    __shared__ int   scnt;
    __shared__ int   sbase;

    const int tid  = threadIdx.x;
    const int j    = blockIdx.z;
    const int gx0a = blockIdx.x * TW - 4;   // 4-aligned tile base
    const int gy0  = blockIdx.y * TH - 2;
    const float* hj = heat + (size_t)j * HW;

    if (tid == 0) scnt = 0;

    // ---- load: mostly float4, per-task fallback at borders ----
    for (int i = tid; i < LR * LCV; i += NMS_T) {
        int ly = i / LCV, lx4 = i - ly * LCV;
        int gy = gy0 + ly;
        int gxs = gx0a + 4 * lx4;
        float4 v;
        bool rowIn = ((unsigned)gy < HH);
        if (rowIn && gxs >= 0 && gxs + 3 < WW) {
            v = __ldg((const float4*)(hj + gy * WW + gxs));
        } else if (rowIn) {
            v.x = ((unsigned)(gxs + 0) < WW) ? __ldg(hj + gy * WW + gxs + 0) : -FLT_MAX;
            v.y = ((unsigned)(gxs + 1) < WW) ? __ldg(hj + gy * WW + gxs + 1) : -FLT_MAX;
            v.z = ((unsigned)(gxs + 2) < WW) ? __ldg(hj + gy * WW + gxs + 2) : -FLT_MAX;
            v.w = ((unsigned)(gxs + 3) < WW) ? __ldg(hj + gy * WW + gxs + 3) : -FLT_MAX;
        } else {
            v = make_float4(-FLT_MAX, -FLT_MAX, -FLT_MAX, -FLT_MAX);
        }
        *(float4*)&s[ly][4 * lx4] = v;
    }
    __syncthreads();

    // ---- horizontal 5-max: 4 outputs/task via float4 ----
    for (int i = tid; i < LR * 32; i += NMS_T) {
        int ly = i >> 5, q = i & 31;
        float4 a = *(const float4*)&s[ly][4 * q];
        float4 b = *(const float4*)&s[ly][4 * q + 4];
        float4 c = *(const float4*)&s[ly][4 * q + 8];
        float v2 = a.z, v3 = a.w;
        float v4 = b.x, v5 = b.y, v6 = b.z, v7 = b.w;
        float v8 = c.x, v9 = c.y;
        float m34 = fmaxf(v3, v4), m56 = fmaxf(v5, v6), m78 = fmaxf(v7, v8);
        float4 o;
        o.x = fmaxf(v2, fmaxf(m34, m56));
        o.y = fmaxf(m34, fmaxf(m56, v7));
        o.z = fmaxf(v4, fmaxf(m56, m78));
        o.w = fmaxf(m56, fmaxf(m78, v9));
        *(float4*)&rm[ly][4 * q] = o;
    }
    __syncthreads();

    // ---- vertical 5-max, 4 output rows per thread (shared partials) ----
    {
        const int tx  = tid & 127;
        const int ty0 = (tid >> 7) * 4;
        float a0 = rm[ty0 + 0][tx], a1 = rm[ty0 + 1][tx];
        float a2 = rm[ty0 + 2][tx], a3 = rm[ty0 + 3][tx];
        float a4 = rm[ty0 + 4][tx], a5 = rm[ty0 + 5][tx];
        float a6 = rm[ty0 + 6][tx], a7 = rm[ty0 + 7][tx];
        float t12 = fmaxf(a1, a2), t34 = fmaxf(a3, a4), t56 = fmaxf(a5, a6);
        float mm[4];
        mm[0] = fmaxf(a0, fmaxf(t12, t34));
        mm[1] = fmaxf(t12, fmaxf(t34, a5));
        mm[2] = fmaxf(a2, fmaxf(t34, t56));
        mm[3] = fmaxf(t34, fmaxf(t56, a7));
        float cc[4];
        cc[0] = s[ty0 + 2][tx + 4];
        cc[1] = s[ty0 + 3][tx + 4];
        cc[2] = s[ty0 + 4][tx + 4];
        cc[3] = s[ty0 + 5][tx + 4];
        const int gx  = blockIdx.x * TW + tx;
        const int gyb = blockIdx.y * TH + ty0;
#pragma unroll
        for (int r = 0; r < 4; r++) {
            if (cc[r] == mm[r]) {
                int idx = (gyb + r) * WW + gx;
                int p = atomicAdd(&scnt, 1);
                if (p < STAGE) { stv[p] = cc[r]; sti[p] = idx; }
                if (cc[r] > HTHR) {
                    int hp = atomicAdd(&g_cnth[j], 1);
                    if (hp < HICAP) { g_hval[j][hp] = cc[r]; g_hidx[j][hp] = idx; }
                }
            }
        }
    }
    __syncthreads();

    if (tid == 0) sbase = atomicAdd(&g_count[j], min(scnt, STAGE));
    __syncthreads();

    const int cnt = min(scnt, STAGE), base = sbase;
    for (int i = tid; i < cnt; i += NMS_T) {
        int d = base + i;
        if (d < MAXPEAKS) {
            g_pval[j][d] = stv[i];
            g_pidx[j][d] = sti[i];
        }
    }
}

// ---------------- kernel 2: top-30 per joint + heat_xy ----------------------
__device__ __forceinline__ bool better(float v1, int i1, float v2, int i2) {
    // descending value, ascending index tie-break (jax.lax.top_k stable order)
    return (v1 > v2) || (v1 == v2 && i1 < i2);
}

template <int NR>
__device__ __forceinline__ void warp_top30(float* v, int* id, float* outv, int* outi) {
    for (int r = 0; r < TOPK; r++) {
        float bv = -FLT_MAX;
        int   bi = 0x7fffffff;
#pragma unroll
        for (int s = 0; s < NR; s++)
            if (better(v[s], id[s], bv, bi)) { bv = v[s]; bi = id[s]; }
#pragma unroll
        for (int o = 16; o > 0; o >>= 1) {
            float ov = __shfl_down_sync(0xffffffffu, bv, o);
            int   oi = __shfl_down_sync(0xffffffffu, bi, o);
            if (better(ov, oi, bv, bi)) { bv = ov; bi = oi; }
        }
        bv = __shfl_sync(0xffffffffu, bv, 0);
        bi = __shfl_sync(0xffffffffu, bi, 0);
        if ((threadIdx.x & 31) == 0) { outv[r] = bv; outi[r] = bi; }
#pragma unroll
        for (int s = 0; s < NR; s++)
            if (id[s] == bi) v[s] = -FLT_MAX;  // winner ids unique
    }
}

__global__ void __launch_bounds__(1024) topk_kernel(const float* __restrict__ off,
                                                    const int* __restrict__ stride_p) {
    __shared__ float wv1[32][TOPK];
    __shared__ int   wi1[32][TOPK];
    __shared__ float wv2[8][TOPK];
    __shared__ int   wi2[8][TOPK];
    __shared__ float fv[TOPK];
    __shared__ int   fi[TOPK];

    const int tid  = threadIdx.x;
    const int w    = tid >> 5;
    const int lane = tid & 31;
    const int j    = blockIdx.x;

    const int n_high = g_cnth[j];
    const bool useHigh = (n_high >= TOPK) && (n_high <= HICAP);

    if (useHigh) {
        float v[1];
        int   id[1];
        if (tid < n_high) { v[0] = g_hval[j][tid]; id[0] = g_hidx[j][tid]; }
        else              { v[0] = -FLT_MAX;       id[0] = 0x7fffffff;     }
        warp_top30<1>(v, id, wv1[w], wi1[w]);
    } else {
        int n = g_count[j];
        if (n > MAXPEAKS) n = MAXPEAKS;
        float v[16];
        int   id[16];
#pragma unroll
        for (int s = 0; s < 16; s++) {
            int i = tid + s * 1024;
            if (i < n) { v[s] = g_pval[j][i]; id[s] = g_pidx[j][i]; }
            else       { v[s] = -FLT_MAX;     id[s] = 0x7fffffff;   }
        }
        warp_top30<16>(v, id, wv1[w], wi1[w]);
    }
    __syncthreads();

    if (w < 8) {
        float v2[4];
        int   id2[4];
#pragma unroll
        for (int s = 0; s < 4; s++) {
            int e = lane + 32 * s;
            if (e < 4 * TOPK) {
                int L = w * 4 + e / TOPK, r = e % TOPK;
                v2[s] = wv1[L][r]; id2[s] = wi1[L][r];
            } else { v2[s] = -FLT_MAX; id2[s] = 0x7fffffff; }
        }
        warp_top30<4>(v2, id2, wv2[w], wi2[w]);
    }
    __syncthreads();

    if (w == 0) {
        float v3[8];
        int   id3[8];
#pragma unroll
        for (int s = 0; s < 8; s++) {
            int e = lane + 32 * s;
            if (e < 8 * TOPK) {
                int L = e / TOPK, r = e % TOPK;
                v3[s] = wv2[L][r]; id3[s] = wi2[L][r];
            } else { v3[s] = -FLT_MAX; id3[s] = 0x7fffffff; }
        }
        warp_top30<8>(v3, id3, fv, fi);
    }
    __syncthreads();

    if (tid < TOPK) {
        int idx = fi[tid];
        if (idx < 0 || idx >= HW) idx = 0;
        float x = (float)(idx & (WW - 1));
        float y = (float)(idx >> 9);
        float ox = __ldg(off + (size_t)(j * 2 + 0) * HW + idx);
        float oy = __ldg(off + (size_t)(j * 2 + 1) * HW + idx);
        float st = (float)(*stride_p);
        float2 r2;
        r2.x = __fmul_rn(st, __fadd_rn(x, ox));   // bit-exact vs reference
        r2.y = __fmul_rn(st, __fadd_rn(y, oy));
        g_hxy[j][tid] = r2;
    }

    // reset counters for next graph replay (all reads happened before syncs)
    if (tid == 0) { g_count[j] = 0; g_cnth[j] = 0; }
}

// ---------------- kernel 3: nearest-candidate assignment --------------------
// 64 poses x 4 joint-groups per 256-thread block. group = warp/2 -> j is
// warp-uniform (broadcast candidate LDS), 4x the warps of pose-per-thread
// (12.5k chip-wide) with 4-5 serial joints/thread for ILP. Math per (pose,
// joint) is the proven R11 body (bit-exact vs reference).
#define APB 64                       // poses per block
#define ABT 256

__global__ void __launch_bounds__(ABT) assign_kernel(const float* __restrict__ poses,
                                                     float* __restrict__ out,
                                                     int N) {
    __shared__ unsigned long long sCX[NJOINT][16];  // packed (-x0,-x1) pairs
    __shared__ unsigned long long sCY[NJOINT][16];
    __shared__ float tile[APB * 34];                // pose in, result out

    const int tid   = threadIdx.x;
    const int w     = tid >> 5;                    // 0..7
    const int lane  = tid & 31;
    const int grp   = w >> 1;                      // 0..3, uniform per warp
    const int prow  = (w & 1) * 32 + lane;         // pose slot 0..63
    const int base  = blockIdx.x * APB;
    const int npose = min(APB, N - base);

    for (int i = tid; i < NJOINT * (TOPK / 2); i += ABT) {
        int jj = i / (TOPK / 2), q = i % (TOPK / 2);
        float2 a = g_hxy[jj][2 * q];
        float2 b = g_hxy[jj][2 * q + 1];
        sCX[jj][q] = pk2(-a.x, -b.x);
        sCY[jj][q] = pk2(-a.y, -b.y);
    }
    {   // coalesced pose tile load (float2)
        const float2* src = (const float2*)(poses + (size_t)base * 34);
        float2* dst = (float2*)tile;
        for (int i = tid; i < npose * NJOINT; i += ABT) dst[i] = src[i];
    }
    __syncthreads();

    if (prow < npose) {
        float* mypose = tile + prow * 34;
        // joints {grp, grp+4, grp+8, grp+12} (+16 for grp 0)
#pragma unroll 1
        for (int j = grp; j < NJOINT; j += 4) {
            const float2 pj = *(const float2*)(mypose + 2 * j);
            const float px = pj.x, py = pj.y;
            const unsigned long long pxx = pk2(px, px);
            const unsigned long long pyy = pk2(py, py);

            float d2a[TOPK];
#pragma unroll
            for (int q = 0; q < TOPK / 2; q++) {
                unsigned long long dx = add2(pxx, sCX[j][q]);
                unsigned long long dy = add2(pyy, sCY[j][q]);
                unsigned long long d2 = fma2(dy, dy, mul2(dx, dx));
                upk2(d2a[2 * q], d2a[2 * q + 1], d2);
            }

            // 4-chain min for ILP
            float b0 = d2a[0], b1 = d2a[1], b2 = d2a[2], b3 = d2a[3];
#pragma unroll
            for (int k = 4; k < TOPK; k += 4) {
                b0 = fminf(b0, d2a[k]);
                b1 = fminf(b1, d2a[k + 1]);
                b2 = fminf(b2, d2a[k + 2]);
                b3 = fminf(b3, d2a[k + 3]);
            }
            b0 = fminf(b0, d2a[28]); b1 = fminf(b1, d2a[29]);
            const float bd = fminf(fminf(b0, b1), fminf(b2, b3));

            // close-set count + first-occurrence argmin (descending overwrite)
            const float thr = __fmul_rn(bd, 1.0000012f);
            int best = 0, nclose = 0;
#pragma unroll
            for (int k = TOPK - 1; k >= 0; k--) {
                if (d2a[k] <= thr) nclose++;
                if (d2a[k] == bd) best = k;
            }

            if (nclose != 1) {
                // rare slow path: replicate reference verbatim (rn d2, IEEE
                // sqrt, first-occurrence argmin over sqrt values)
                float bs = FLT_MAX;
                best = 0;
                for (int k = 0; k < TOPK; k++) {
                    float lo, hi, ncx, ncy;
                    upk2(lo, hi, sCX[j][k >> 1]); ncx = (k & 1) ? hi : lo;
                    upk2(lo, hi, sCY[j][k >> 1]); ncy = (k & 1) ? hi : lo;
                    float dx = __fadd_rn(px, ncx);
                    float dy = __fadd_rn(py, ncy);
                    float d  = __fadd_rn(__fmul_rn(dx, dx), __fmul_rn(dy, dy));
                    float sq = sqrtf(d);
                    if (sq < bs) { bs = sq; best = k; }
                }
            }

            float lo, hi, rx, ry;
            upk2(lo, hi, sCX[j][best >> 1]);
            rx = (best & 1) ? -hi : -lo;
            upk2(lo, hi, sCY[j][best >> 1]);
            ry = (best & 1) ? -hi : -lo;

            // own (pose, joint) slot: read once above, written once here
            *(float2*)(mypose + 2 * j) = make_float2(rx, ry);
        }
    }
    __syncthreads();

    {   // coalesced result store (float2)
        float2* dst = (float2*)(out + (size_t)base * 34);
        const float2* src = (const float2*)tile;
        for (int i = tid; i < npose * NJOINT; i += ABT) dst[i] = src[i];
    }
}

// ---------------- launch ----------------------------------------------------
extern "C" void kernel_launch(void* const* d_in, const int* in_sizes, int n_in,
                              void* d_out, int out_size) {
    const float* poses    = (const float*)d_in[0];   // (N, 34) f32
    const float* heat     = (const float*)d_in[1];   // (17, 512, 512) f32
    const float* off      = (const float*)d_in[2];   // (17, 2, 512, 512) f32
    const int*   stride_p = (const int*)d_in[3];     // scalar

    const int N = in_sizes[0] / 34;

    dim3 g_nms(WW / TW, HH / TH, NJOINT);            // (4, 32, 17)
    nms_kernel<<<g_nms, NMS_T>>>(heat);

    topk_kernel<<<NJOINT, 1024>>>(off, stride_p);

    assign_kernel<<<(N + APB - 1) / APB, ABT>>>(poses, (float*)d_out, N);
}